// round 16
// baseline (speedup 1.0000x reference)
#include <cuda_runtime.h>
#include <cuda_fp16.h>
#include <math.h>

// ---------------------------------------------------------------------------
// DenseCRF mean-field with permutohedral lattice filtering.
// 21-ch lattice buffers stored as fp16 (24 padded ch = 48B rows = 3 uint4),
// NATIVE half2 blur arithmetic, ONE THREAD PER ROW blur (sector-efficient
// 48B gathers), fp32 slice/softmax compute, fp32 1-ch normalization chain,
// fused update+splat (4 lanes/pixel), merged bi/sp launches, triple-buffered
// with zero riding in blur pass 0.                    [R13 + row-blur]
// ---------------------------------------------------------------------------

#define CC 21
#define GRPH 3                      // uint4 groups per fp16 row (8 halves each)
static constexpr int       NPIX    = 512 * 512;
static constexpr long long ROWS_BI = 6LL * NPIX + 1;
static constexpr long long ROWS_SP = 3LL * NPIX + 1;

// fp16 value buffers (uint4 = 8 halves)
__device__ uint4 g_hb0[ROWS_BI * GRPH];
__device__ uint4 g_hb1[ROWS_BI * GRPH];
__device__ uint4 g_hb2[ROWS_BI * GRPH];
__device__ uint4 g_hs0[ROWS_SP * GRPH];
__device__ uint4 g_hs1[ROWS_SP * GRPH];
__device__ uint4 g_hs2[ROWS_SP * GRPH];
// fp32 1-channel norm-chain scratch
__device__ float g_v1a[ROWS_BI], g_v1b[ROWS_BI];
__device__ float g_w1a[ROWS_SP], g_w1b[ROWS_SP];
// per-pixel norms
__device__ float g_nbi[NPIX];
__device__ float g_nsp[NPIX];

__device__ __forceinline__ uint4* hbi(int i) { return i == 0 ? g_hb0 : (i == 1 ? g_hb1 : g_hb2); }
__device__ __forceinline__ uint4* hsp(int i) { return i == 0 ? g_hs0 : (i == 1 ? g_hs1 : g_hs2); }
__device__ __forceinline__ float* n1bi(int i) { return i ? g_v1b : g_v1a; }
__device__ __forceinline__ float* n1sp(int i) { return i ? g_w1b : g_w1a; }

__device__ __forceinline__ unsigned pack2(float a, float b) {
    __half2 h = __floats2half2_rn(a, b);
    return *reinterpret_cast<unsigned*>(&h);
}
__device__ __forceinline__ float2 unp2(unsigned u) {
    __half2 h = *reinterpret_cast<__half2*>(&u);
    return __half22float2(h);
}
// native half2: a + 0.5*(b+c)  -> HADD2 + HFMA2 (no f32 converts)
__device__ __forceinline__ unsigned comb2(unsigned a, unsigned b, unsigned c) {
    __half2 ha = *reinterpret_cast<__half2*>(&a);
    __half2 hb = *reinterpret_cast<__half2*>(&b);
    __half2 hc = *reinterpret_cast<__half2*>(&c);
    __half2 half_ = __floats2half2_rn(0.5f, 0.5f);
    __half2 o = __hfma2(half_, __hadd2(hb, hc), ha);
    return *reinterpret_cast<unsigned*>(&o);
}
__device__ __forceinline__ uint4 comb4(uint4 a, uint4 b, uint4 c) {
    uint4 o;
    o.x = comb2(a.x, b.x, c.x);
    o.y = comb2(a.y, b.y, c.y);
    o.z = comb2(a.z, b.z, c.z);
    o.w = comb2(a.w, b.w, c.w);
    return o;
}
__device__ __forceinline__ void red4h(uint4* p, unsigned a, unsigned b, unsigned c, unsigned d) {
    asm volatile("red.global.add.noftz.v4.f16x2 [%0], {%1, %2, %3, %4};"
                 :: "l"(p), "r"(a), "r"(b), "r"(c), "r"(d) : "memory");
}

// FFMA-only e^x for x <= 0 (clamped at -80).
__device__ __forceinline__ float fexp(float x) {
    x = fmaxf(x, -80.0f);
    float t  = x * 1.4426950408889634f;      // log2(e)
    float fl = floorf(t);
    float f  = t - fl;
    float p = 1.5403530e-4f;
    p = p * f + 1.3333558e-3f;
    p = p * f + 9.6181291e-3f;
    p = p * f + 5.5504109e-2f;
    p = p * f + 2.4022651e-1f;
    p = p * f + 6.9314718e-1f;
    p = p * f + 1.0f;
    return __int_as_float(__float_as_int(p) + ((int)fl << 23));
}

// ---------------------------------------------------------------------------

__global__ __launch_bounds__(256) void k_zero_fronts(long long na, long long nb) {
    long long i = (long long)blockIdx.x * blockDim.x + threadIdx.x;
    if (i >= na + nb) return;
    if (i < na) g_v1a[i]      = 0.0f;
    else        g_w1a[i - na] = 0.0f;
}

// 1-ch splat for both lattices + zero two fp16 buffers (uint4 counts)
__global__ __launch_bounds__(256) void k_splat1z(const float* __restrict__ ws_bi,
                                                 const int* __restrict__ os_bi, int N6,
                                                 const float* __restrict__ ws_sp,
                                                 const int* __restrict__ os_sp, int N3,
                                                 long long zna, long long znb) {
    long long i = (long long)blockIdx.x * blockDim.x + threadIdx.x;
    if (i < N6) { atomicAdd(g_v1a + os_bi[i], ws_bi[i]); return; }
    if (i < N6 + N3) { long long j = i - N6; atomicAdd(g_w1a + os_sp[j], ws_sp[j]); return; }
    long long z = i - (N6 + N3);
    uint4 zz = make_uint4(0, 0, 0, 0);
    if (z < zna)            g_hb2[z]       = zz;
    else if (z < zna + znb) g_hs2[z - zna] = zz;
}

__global__ __launch_bounds__(256) void k_blur1_both(int bd, int bs,
                                                    const int* __restrict__ nbr_b, int Mb,
                                                    int sd, int ss,
                                                    const int* __restrict__ nbr_s, int Ms,
                                                    int hassp) {
    int nb = Mb + 1;
    int ns = hassp ? (Ms + 1) : 0;
    int i = blockIdx.x * blockDim.x + threadIdx.x;
    if (i >= nb + ns) return;
    float* dst; const float* src; const int* nbr; int r;
    if (i < nb) { dst = n1bi(bd); src = n1bi(bs); nbr = nbr_b; r = i; }
    else        { dst = n1sp(sd); src = n1sp(ss); nbr = nbr_s; r = i - nb; }
    if (r == 0) { dst[0] = 0.0f; return; }
    int2 nn = ((const int2*)nbr)[r - 1];
    dst[r] = src[r] + 0.5f * (src[nn.x] + src[nn.y]);
}

// ---- fp16 24-ch blur, ONE THREAD PER ROW, bi+sp merged, optional zero tail ----
__global__ __launch_bounds__(256) void k_blurHz(int bd, int bs,
                                                const int* __restrict__ nbr_b, int Mb,
                                                int sd, int ss,
                                                const int* __restrict__ nbr_s, int Ms,
                                                int hassp,
                                                int zbi, long long zna,
                                                int zsp, long long znb) {
    long long nbt = (long long)(Mb + 1);
    long long nst = hassp ? (long long)(Ms + 1) : 0;
    long long idx = (long long)blockIdx.x * blockDim.x + threadIdx.x;
    if (idx < nbt + nst) {
        uint4* dst; const uint4* src; const int* nbr; int r;
        if (idx < nbt) { dst = hbi(bd); src = hbi(bs); nbr = nbr_b; r = (int)idx; }
        else           { dst = hsp(sd); src = hsp(ss); nbr = nbr_s; r = (int)(idx - nbt); }
        if (r == 0) {
            uint4 zz = make_uint4(0, 0, 0, 0);
            dst[0] = zz; dst[1] = zz; dst[2] = zz;
            return;
        }
        int2 nn = ((const int2*)nbr)[r - 1];
        const uint4* sa = src + (long long)r    * GRPH;
        const uint4* sb = src + (long long)nn.x * GRPH;
        const uint4* sc = src + (long long)nn.y * GRPH;
        uint4 a0 = sa[0], a1 = sa[1], a2 = sa[2];
        uint4 b0 = sb[0], b1 = sb[1], b2 = sb[2];
        uint4 c0 = sc[0], c1 = sc[1], c2 = sc[2];
        uint4* d = dst + (long long)r * GRPH;
        d[0] = comb4(a0, b0, c0);
        d[1] = comb4(a1, b1, c1);
        d[2] = comb4(a2, b2, c2);
        return;
    }
    long long z = idx - (nbt + nst);
    uint4 zz = make_uint4(0, 0, 0, 0);
    if (z < zna)            hbi(zbi)[z]       = zz;
    else if (z < zna + znb) hsp(zsp)[z - zna] = zz;
}

// ---- fused [norm +] slice(bi)+slice(sp)+softmax+Q (+splat into next buffers) ----
// 4 lanes per pixel; lanes 0..2 own 8 channels each (24 padded), lane 3 idle.
__global__ __launch_bounds__(256) void k_update_splat(
        const float* __restrict__ u, float* __restrict__ extout,
        const float* __restrict__ ws_bi, const int* __restrict__ os_bi,
        const float* __restrict__ ws_sp, const int* __restrict__ os_sp,
        int N, int usepair, int to_ext, int do_splat, int do_norm,
        int rd_bi, int rd_sp, int wr_bi, int wr_sp, float cb, float cs,
        int nv_bi, int nv_sp, float a_bi, float a_sp) {
    int tid = blockIdx.x * blockDim.x + threadIdx.x;
    int n = tid >> 2;
    int g = tid & 3;
    if (n >= N) return;
    bool act = (g < GRPH);

    float wbj[6]; int obj[6];
    float wsj[3]; int osj[3];
#pragma unroll
    for (int j = 0; j < 6; j++) { wbj[j] = ws_bi[n * 6 + j]; obj[j] = os_bi[n * 6 + j]; }
#pragma unroll
    for (int j = 0; j < 3; j++) { wsj[j] = ws_sp[n * 3 + j]; osj[j] = os_sp[n * 3 + j]; }

    float nb, ns;
    if (do_norm) {
        float sb = 0.0f, ss_ = 0.0f;
        if (g == 0) {
            const float* vb = n1bi(nv_bi);
#pragma unroll
            for (int j = 0; j < 6; j++) sb += wbj[j] * vb[obj[j]];
            const float* vs = n1sp(nv_sp);
#pragma unroll
            for (int j = 0; j < 3; j++) ss_ += wsj[j] * vs[osj[j]];
            sb  = 1.0f / (sqrtf(a_bi * sb)  + 1e-20f);
            ss_ = 1.0f / (sqrtf(a_sp * ss_) + 1e-20f);
            g_nbi[n] = sb;
            g_nsp[n] = ss_;
        }
        nb = __shfl_sync(0xffffffffu, sb, 0, 4);
        ns = __shfl_sync(0xffffffffu, ss_, 0, 4);
    } else {
        nb = g_nbi[n];
        ns = g_nsp[n];
    }

    float l[8];
#pragma unroll
    for (int k = 0; k < 8; k++) l[k] = -1e30f;

    if (act) {
        float acc[8];
#pragma unroll
        for (int k = 0; k < 8; k++) acc[k] = 0.0f;
        if (usepair) {
            const uint4* vb = hbi(rd_bi);
            float pb = cb * nb;
#pragma unroll
            for (int j = 0; j < 6; j++) {
                float w = wbj[j] * pb;
                uint4 v = vb[(long long)obj[j] * GRPH + g];
                float2 f0 = unp2(v.x), f1 = unp2(v.y), f2 = unp2(v.z), f3 = unp2(v.w);
                acc[0] += w * f0.x; acc[1] += w * f0.y;
                acc[2] += w * f1.x; acc[3] += w * f1.y;
                acc[4] += w * f2.x; acc[5] += w * f2.y;
                acc[6] += w * f3.x; acc[7] += w * f3.y;
            }
            const uint4* vs = hsp(rd_sp);
            float ps = cs * ns;
#pragma unroll
            for (int j = 0; j < 3; j++) {
                float w = wsj[j] * ps;
                uint4 v = vs[(long long)osj[j] * GRPH + g];
                float2 f0 = unp2(v.x), f1 = unp2(v.y), f2 = unp2(v.z), f3 = unp2(v.w);
                acc[0] += w * f0.x; acc[1] += w * f0.y;
                acc[2] += w * f1.x; acc[3] += w * f1.y;
                acc[4] += w * f2.x; acc[5] += w * f2.y;
                acc[6] += w * f3.x; acc[7] += w * f3.y;
            }
        }
        int c0 = g * 8;
        long long ub = (long long)n * CC + c0;
#pragma unroll
        for (int k = 0; k < 8; k++)
            if (c0 + k < CC) l[k] = acc[k] - u[ub + k];
    }

    // softmax across the 4-lane group (24 padded channels; pads -> exp = 0)
    float mx = l[0];
#pragma unroll
    for (int k = 1; k < 8; k++) mx = fmaxf(mx, l[k]);
#pragma unroll
    for (int d = 1; d < 4; d <<= 1)
        mx = fmaxf(mx, __shfl_xor_sync(0xffffffffu, mx, d, 4));
    float e[8], s = 0.0f;
#pragma unroll
    for (int k = 0; k < 8; k++) { e[k] = fexp(l[k] - mx); s += e[k]; }
#pragma unroll
    for (int d = 1; d < 4; d <<= 1)
        s += __shfl_xor_sync(0xffffffffu, s, d, 4);
    float inv = 1.0f / s;

    if (act) {
        float q[8];
#pragma unroll
        for (int k = 0; k < 8; k++) q[k] = e[k] * inv;
        if (to_ext) {
            int c0 = g * 8;
            long long ob = (long long)n * CC + c0;
#pragma unroll
            for (int k = 0; k < 8; k++)
                if (c0 + k < CC) extout[ob + k] = q[k];
        }
        if (do_splat) {
            uint4* vb = hbi(wr_bi);
#pragma unroll
            for (int j = 0; j < 6; j++) {
                float w = wbj[j] * nb;
                red4h(vb + (long long)obj[j] * GRPH + g,
                      pack2(w * q[0], w * q[1]), pack2(w * q[2], w * q[3]),
                      pack2(w * q[4], w * q[5]), pack2(w * q[6], w * q[7]));
            }
            uint4* vs = hsp(wr_sp);
#pragma unroll
            for (int j = 0; j < 3; j++) {
                float w = wsj[j] * ns;
                red4h(vs + (long long)osj[j] * GRPH + g,
                      pack2(w * q[0], w * q[1]), pack2(w * q[2], w * q[3]),
                      pack2(w * q[4], w * q[5]), pack2(w * q[6], w * q[7]));
            }
        }
    }
}

// ---------------------------------------------------------------------------

static inline unsigned gridFor(long long n) { return (unsigned)((n + 255) / 256); }

extern "C" void kernel_launch(void* const* d_in, const int* in_sizes, int n_in,
                              void* d_out, int out_size) {
    const float* unary  = (const float*)d_in[0];
    const float* ws_bi  = (const float*)d_in[1];
    const float* ws_sp  = (const float*)d_in[2];
    const int*   os_bi  = (const int*)  d_in[3];
    const int*   os_sp  = (const int*)  d_in[4];
    const int*   nbr_bi = (const int*)  d_in[5];
    const int*   nbr_sp = (const int*)  d_in[6];
    float*       out    = (float*)d_out;

    const int N   = in_sizes[1] / 6;
    const int Mbi = in_sizes[5] / 12;
    const int Msp = in_sizes[6] / 6;
    const float ALPHA_BI = 32.0f / 33.0f;  // 1/(1+2^-5)
    const float ALPHA_SP = 0.8f;           // 1/(1+2^-2)
    const float CB = 10.0f * ALPHA_BI;
    const float CS = 3.0f  * ALPHA_SP;
    const int B = 256;

    const long long NBH = (long long)(Mbi + 1) * GRPH;   // fp16 buffer in uint4s
    const long long NSH = (long long)(Msp + 1) * GRPH;

    // ---- prologue: normalization constants (fp32 1-channel chain) ----
    k_zero_fronts<<<gridFor((Mbi + 1) + (Msp + 1)), B>>>(Mbi + 1, Msp + 1);
    k_splat1z<<<gridFor((long long)N * 9 + NBH + NSH), B>>>(
        ws_bi, os_bi, N * 6, ws_sp, os_sp, N * 3, NBH, NSH);
    int cb_ = 0, cs_ = 0;
    for (int j = 0; j < 6; j++) {
        int hassp = (j < 3);
        int bd = 1 - cb_;
        int sd = 1 - cs_;
        long long tot = (Mbi + 1) + (hassp ? (Msp + 1) : 0);
        k_blur1_both<<<gridFor(tot), B>>>(bd, cb_, nbr_bi + (long long)j * Mbi * 2, Mbi,
                                          sd, cs_, nbr_sp + (long long)j * Msp * 2, Msp, hassp);
        cb_ = bd;
        if (hassp) cs_ = sd;
    }
    // bi 1-ch final in buffer cb_ (=0), sp in cs_ (=1)

    // ---- initial Q = softmax(-u): computes norms inline, splats into bi2/sp2 ----
    k_update_splat<<<gridFor((long long)N * 4), B>>>(
        unary, out, ws_bi, os_bi, ws_sp, os_sp, N,
        /*usepair=*/0, /*to_ext=*/0, /*do_splat=*/1, /*do_norm=*/1,
        0, 0, /*wr_bi=*/2, /*wr_sp=*/2, CB, CS,
        cb_, cs_, ALPHA_BI, ALPHA_SP);

    // ---- mean-field iterations (triple-buffer rotation) ----
    int sB = 2, tB = 0, zB = 1;   // bi: splat-src / pong / to-zero
    int sS = 2, tS = 0, zS = 1;   // sp
    for (int it = 0; it < 5; it++) {
        int c = sB, csp = sS;
        for (int j = 0; j < 6; j++) {
            int hassp = (j < 3);
            int d   = (c   == sB) ? tB : sB;
            int dsp = (csp == sS) ? tS : sS;
            long long tot = (Mbi + 1) + (hassp ? (Msp + 1) : 0)
                          + ((j == 0) ? (NBH + NSH) : 0);
            if (j == 0) {
                k_blurHz<<<gridFor(tot), B>>>(d, c, nbr_bi + (long long)j * Mbi * 2, Mbi,
                                              dsp, csp, nbr_sp + (long long)j * Msp * 2, Msp,
                                              hassp, zB, NBH, zS, NSH);
            } else {
                k_blurHz<<<gridFor(tot), B>>>(d, c, nbr_bi + (long long)j * Mbi * 2, Mbi,
                                              dsp, csp, nbr_sp + (long long)j * Msp * 2, Msp,
                                              hassp, 0, 0, 0, 0);
            }
            c = d;
            if (hassp) csp = dsp;
        }
        // bi result in sB (6 flips), sp result in tS (3 flips)
        if (it < 4) {
            k_update_splat<<<gridFor((long long)N * 4), B>>>(
                unary, out, ws_bi, os_bi, ws_sp, os_sp, N,
                /*usepair=*/1, /*to_ext=*/0, /*do_splat=*/1, /*do_norm=*/0,
                sB, tS, /*wr_bi=*/zB, /*wr_sp=*/zS, CB, CS, 0, 0, 0.f, 0.f);
            int nB_ = zB; zB = sB; sB = nB_;                   // tB unchanged
            int nS_ = zS; zS = tS; tS = sS; sS = nS_;
        } else {
            k_update_splat<<<gridFor((long long)N * 4), B>>>(
                unary, out, ws_bi, os_bi, ws_sp, os_sp, N,
                /*usepair=*/1, /*to_ext=*/1, /*do_splat=*/0, /*do_norm=*/0,
                sB, tS, 0, 0, CB, CS, 0, 0, 0.f, 0.f);
        }
    }
}

// round 17
// speedup vs baseline: 1.1707x; 1.1707x over previous
#include <cuda_runtime.h>
#include <cuda_fp16.h>
#include <math.h>

// ---------------------------------------------------------------------------
// DenseCRF mean-field with permutohedral lattice filtering.
// 21-ch lattice buffers stored as fp16 (24 padded ch = 48B rows = 3 uint4),
// NATIVE half2 blur arithmetic, fp32 slice/softmax compute, fp32 1-ch norm
// chain, fused update+splat (4 lanes/pixel), merged bi/sp launches,
// triple-buffered with zero riding in blur pass 0, and PDL (programmatic
// dependent launch) on every dependent kernel: independent loads (nbr, ws/os)
// run pre-sync, producer-dependent accesses after griddepcontrol.wait.
//                                                   [R13 (514us) + PDL]
// ---------------------------------------------------------------------------

#define CC 21
#define GRPH 3                      // uint4 groups per fp16 row (8 halves each)
static constexpr int       NPIX    = 512 * 512;
static constexpr long long ROWS_BI = 6LL * NPIX + 1;
static constexpr long long ROWS_SP = 3LL * NPIX + 1;

// fp16 value buffers (uint4 = 8 halves)
__device__ uint4 g_hb0[ROWS_BI * GRPH];
__device__ uint4 g_hb1[ROWS_BI * GRPH];
__device__ uint4 g_hb2[ROWS_BI * GRPH];
__device__ uint4 g_hs0[ROWS_SP * GRPH];
__device__ uint4 g_hs1[ROWS_SP * GRPH];
__device__ uint4 g_hs2[ROWS_SP * GRPH];
// fp32 1-channel norm-chain scratch
__device__ float g_v1a[ROWS_BI], g_v1b[ROWS_BI];
__device__ float g_w1a[ROWS_SP], g_w1b[ROWS_SP];
// per-pixel norms
__device__ float g_nbi[NPIX];
__device__ float g_nsp[NPIX];

__device__ __forceinline__ uint4* hbi(int i) { return i == 0 ? g_hb0 : (i == 1 ? g_hb1 : g_hb2); }
__device__ __forceinline__ uint4* hsp(int i) { return i == 0 ? g_hs0 : (i == 1 ? g_hs1 : g_hs2); }
__device__ __forceinline__ float* n1bi(int i) { return i ? g_v1b : g_v1a; }
__device__ __forceinline__ float* n1sp(int i) { return i ? g_w1b : g_w1a; }

// PDL primitives (raw PTX; sm_90+)
__device__ __forceinline__ void pdl_wait()    { asm volatile("griddepcontrol.wait;" ::: "memory"); }
__device__ __forceinline__ void pdl_trigger() { asm volatile("griddepcontrol.launch_dependents;" ::: "memory"); }

__device__ __forceinline__ unsigned pack2(float a, float b) {
    __half2 h = __floats2half2_rn(a, b);
    return *reinterpret_cast<unsigned*>(&h);
}
__device__ __forceinline__ float2 unp2(unsigned u) {
    __half2 h = *reinterpret_cast<__half2*>(&u);
    return __half22float2(h);
}
// native half2: a + 0.5*(b+c)  -> HADD2 + HFMA2 (no f32 converts)
__device__ __forceinline__ unsigned comb2(unsigned a, unsigned b, unsigned c) {
    __half2 ha = *reinterpret_cast<__half2*>(&a);
    __half2 hb = *reinterpret_cast<__half2*>(&b);
    __half2 hc = *reinterpret_cast<__half2*>(&c);
    __half2 half_ = __floats2half2_rn(0.5f, 0.5f);
    __half2 o = __hfma2(half_, __hadd2(hb, hc), ha);
    return *reinterpret_cast<unsigned*>(&o);
}
__device__ __forceinline__ void red4h(uint4* p, unsigned a, unsigned b, unsigned c, unsigned d) {
    asm volatile("red.global.add.noftz.v4.f16x2 [%0], {%1, %2, %3, %4};"
                 :: "l"(p), "r"(a), "r"(b), "r"(c), "r"(d) : "memory");
}

// FFMA-only e^x for x <= 0 (clamped at -80).
__device__ __forceinline__ float fexp(float x) {
    x = fmaxf(x, -80.0f);
    float t  = x * 1.4426950408889634f;      // log2(e)
    float fl = floorf(t);
    float f  = t - fl;
    float p = 1.5403530e-4f;
    p = p * f + 1.3333558e-3f;
    p = p * f + 9.6181291e-3f;
    p = p * f + 5.5504109e-2f;
    p = p * f + 2.4022651e-1f;
    p = p * f + 6.9314718e-1f;
    p = p * f + 1.0f;
    return __int_as_float(__float_as_int(p) + ((int)fl << 23));
}

// ---------------------------------------------------------------------------

__global__ __launch_bounds__(256) void k_zero_fronts(long long na, long long nb) {
    long long i = (long long)blockIdx.x * blockDim.x + threadIdx.x;
    if (i < na + nb) {
        if (i < na) g_v1a[i]      = 0.0f;
        else        g_w1a[i - na] = 0.0f;
    }
    pdl_trigger();
}

// 1-ch splat for both lattices + zero two fp16 buffers (uint4 counts)
__global__ __launch_bounds__(256) void k_splat1z(const float* __restrict__ ws_bi,
                                                 const int* __restrict__ os_bi, int N6,
                                                 const float* __restrict__ ws_sp,
                                                 const int* __restrict__ os_sp, int N3,
                                                 long long zna, long long znb) {
    long long i = (long long)blockIdx.x * blockDim.x + threadIdx.x;
    // pre-sync: load independent inputs
    float w = 0.0f; int o = 0; int mode = 2;
    if (i < N6)            { w = ws_bi[i]; o = os_bi[i]; mode = 0; }
    else if (i < N6 + N3)  { long long j = i - N6; w = ws_sp[j]; o = os_sp[j]; mode = 1; }
    pdl_wait();
    if (mode == 0)      atomicAdd(g_v1a + o, w);
    else if (mode == 1) atomicAdd(g_w1a + o, w);
    else {
        long long z = i - (N6 + N3);
        uint4 zz = make_uint4(0, 0, 0, 0);
        if (z < zna)            g_hb2[z]       = zz;
        else if (z < zna + znb) g_hs2[z - zna] = zz;
    }
    pdl_trigger();
}

__global__ __launch_bounds__(256) void k_blur1_both(int bd, int bs,
                                                    const int* __restrict__ nbr_b, int Mb,
                                                    int sd, int ss,
                                                    const int* __restrict__ nbr_s, int Ms,
                                                    int hassp) {
    int nb = Mb + 1;
    int ns = hassp ? (Ms + 1) : 0;
    int i = blockIdx.x * blockDim.x + threadIdx.x;
    bool on = (i < nb + ns);
    float* dst = 0; const float* src = 0; int r = 0;
    int2 nn = make_int2(0, 0);
    if (on) {   // pre-sync: nbr tables are kernel-independent inputs
        const int* nbr;
        if (i < nb) { dst = n1bi(bd); src = n1bi(bs); nbr = nbr_b; r = i; }
        else        { dst = n1sp(sd); src = n1sp(ss); nbr = nbr_s; r = i - nb; }
        if (r > 0) nn = ((const int2*)nbr)[r - 1];
    }
    pdl_wait();
    if (on) {
        if (r == 0) dst[0] = 0.0f;
        else        dst[r] = src[r] + 0.5f * (src[nn.x] + src[nn.y]);
    }
    pdl_trigger();
}

// ---- fp16 24-ch blur, bi+sp merged, optional zero tail ----
__global__ __launch_bounds__(256) void k_blurHz(int bd, int bs,
                                                const int* __restrict__ nbr_b, int Mb,
                                                int sd, int ss,
                                                const int* __restrict__ nbr_s, int Ms,
                                                int hassp,
                                                int zbi, long long zna,
                                                int zsp, long long znb) {
    long long nbt = (long long)(Mb + 1) * GRPH;
    long long nst = hassp ? (long long)(Ms + 1) * GRPH : 0;
    long long idx = (long long)blockIdx.x * blockDim.x + threadIdx.x;
    bool on = (idx < nbt + nst);
    uint4* dst = 0; const uint4* src = 0; long long rel = 0; int r = 0, g = 0;
    int2 nn = make_int2(0, 0);
    if (on) {   // pre-sync: indexing + nbr load (independent of producer)
        const int* nbr;
        if (idx < nbt) { dst = hbi(bd); src = hbi(bs); nbr = nbr_b; rel = idx; }
        else           { dst = hsp(sd); src = hsp(ss); nbr = nbr_s; rel = idx - nbt; }
        r = (int)(rel / GRPH);
        g = (int)(rel % GRPH);
        if (r > 0) nn = ((const int2*)nbr)[r - 1];
    }
    pdl_wait();
    if (on) {
        if (r == 0) {
            dst[g] = make_uint4(0, 0, 0, 0);
        } else {
            uint4 a = src[rel];
            uint4 b = src[(long long)nn.x * GRPH + g];
            uint4 c = src[(long long)nn.y * GRPH + g];
            uint4 o;
            o.x = comb2(a.x, b.x, c.x);
            o.y = comb2(a.y, b.y, c.y);
            o.z = comb2(a.z, b.z, c.z);
            o.w = comb2(a.w, b.w, c.w);
            dst[rel] = o;
        }
    } else {
        long long z = idx - (nbt + nst);
        uint4 zz = make_uint4(0, 0, 0, 0);
        if (z < zna)            hbi(zbi)[z]       = zz;
        else if (z < zna + znb) hsp(zsp)[z - zna] = zz;
    }
    pdl_trigger();
}

// ---- fused [norm +] slice(bi)+slice(sp)+softmax+Q (+splat into next buffers) ----
// 4 lanes per pixel; lanes 0..2 own 8 channels each (24 padded), lane 3 idle.
__global__ __launch_bounds__(256) void k_update_splat(
        const float* __restrict__ u, float* __restrict__ extout,
        const float* __restrict__ ws_bi, const int* __restrict__ os_bi,
        const float* __restrict__ ws_sp, const int* __restrict__ os_sp,
        int N, int usepair, int to_ext, int do_splat, int do_norm,
        int rd_bi, int rd_sp, int wr_bi, int wr_sp, float cb, float cs,
        int nv_bi, int nv_sp, float a_bi, float a_sp) {
    int tid = blockIdx.x * blockDim.x + threadIdx.x;
    int n = tid >> 2;
    int g = tid & 3;
    bool on = (n < N);
    bool act = on && (g < GRPH);

    // pre-sync: ws/os/u are external inputs, independent of the producer chain
    float wbj[6]; int obj[6];
    float wsj[3]; int osj[3];
    float uv[8];
    if (on) {
#pragma unroll
        for (int j = 0; j < 6; j++) { wbj[j] = ws_bi[n * 6 + j]; obj[j] = os_bi[n * 6 + j]; }
#pragma unroll
        for (int j = 0; j < 3; j++) { wsj[j] = ws_sp[n * 3 + j]; osj[j] = os_sp[n * 3 + j]; }
    }
    if (act) {
        int c0 = g * 8;
        long long ub = (long long)n * CC + c0;
#pragma unroll
        for (int k = 0; k < 8; k++) uv[k] = (c0 + k < CC) ? u[ub + k] : 0.0f;
    }
    pdl_wait();
    if (!on) { pdl_trigger(); return; }

    float nb = 0.0f, ns = 0.0f;
    if (do_norm) {
        float sb = 0.0f, ss_ = 0.0f;
        if (g == 0) {
            const float* vb = n1bi(nv_bi);
#pragma unroll
            for (int j = 0; j < 6; j++) sb += wbj[j] * vb[obj[j]];
            const float* vs = n1sp(nv_sp);
#pragma unroll
            for (int j = 0; j < 3; j++) ss_ += wsj[j] * vs[osj[j]];
            sb  = 1.0f / (sqrtf(a_bi * sb)  + 1e-20f);
            ss_ = 1.0f / (sqrtf(a_sp * ss_) + 1e-20f);
            g_nbi[n] = sb;
            g_nsp[n] = ss_;
        }
        nb = __shfl_sync(0xffffffffu, sb, 0, 4);
        ns = __shfl_sync(0xffffffffu, ss_, 0, 4);
    } else {
        nb = g_nbi[n];
        ns = g_nsp[n];
    }

    float l[8];
#pragma unroll
    for (int k = 0; k < 8; k++) l[k] = -1e30f;

    if (act) {
        float acc[8];
#pragma unroll
        for (int k = 0; k < 8; k++) acc[k] = 0.0f;
        if (usepair) {
            const uint4* vb = hbi(rd_bi);
            float pb = cb * nb;
#pragma unroll
            for (int j = 0; j < 6; j++) {
                float w = wbj[j] * pb;
                uint4 v = vb[(long long)obj[j] * GRPH + g];
                float2 f0 = unp2(v.x), f1 = unp2(v.y), f2 = unp2(v.z), f3 = unp2(v.w);
                acc[0] += w * f0.x; acc[1] += w * f0.y;
                acc[2] += w * f1.x; acc[3] += w * f1.y;
                acc[4] += w * f2.x; acc[5] += w * f2.y;
                acc[6] += w * f3.x; acc[7] += w * f3.y;
            }
            const uint4* vs = hsp(rd_sp);
            float ps = cs * ns;
#pragma unroll
            for (int j = 0; j < 3; j++) {
                float w = wsj[j] * ps;
                uint4 v = vs[(long long)osj[j] * GRPH + g];
                float2 f0 = unp2(v.x), f1 = unp2(v.y), f2 = unp2(v.z), f3 = unp2(v.w);
                acc[0] += w * f0.x; acc[1] += w * f0.y;
                acc[2] += w * f1.x; acc[3] += w * f1.y;
                acc[4] += w * f2.x; acc[5] += w * f2.y;
                acc[6] += w * f3.x; acc[7] += w * f3.y;
            }
        }
        int c0 = g * 8;
#pragma unroll
        for (int k = 0; k < 8; k++)
            if (c0 + k < CC) l[k] = acc[k] - uv[k];
    }

    // softmax across the 4-lane group (24 padded channels; pads -> exp = 0)
    float mx = l[0];
#pragma unroll
    for (int k = 1; k < 8; k++) mx = fmaxf(mx, l[k]);
#pragma unroll
    for (int d = 1; d < 4; d <<= 1)
        mx = fmaxf(mx, __shfl_xor_sync(0xffffffffu, mx, d, 4));
    float e[8], s = 0.0f;
#pragma unroll
    for (int k = 0; k < 8; k++) { e[k] = fexp(l[k] - mx); s += e[k]; }
#pragma unroll
    for (int d = 1; d < 4; d <<= 1)
        s += __shfl_xor_sync(0xffffffffu, s, d, 4);
    float inv = 1.0f / s;

    if (act) {
        float q[8];
#pragma unroll
        for (int k = 0; k < 8; k++) q[k] = e[k] * inv;
        if (to_ext) {
            int c0 = g * 8;
            long long ob = (long long)n * CC + c0;
#pragma unroll
            for (int k = 0; k < 8; k++)
                if (c0 + k < CC) extout[ob + k] = q[k];
        }
        if (do_splat) {
            uint4* vb = hbi(wr_bi);
#pragma unroll
            for (int j = 0; j < 6; j++) {
                float w = wbj[j] * nb;
                red4h(vb + (long long)obj[j] * GRPH + g,
                      pack2(w * q[0], w * q[1]), pack2(w * q[2], w * q[3]),
                      pack2(w * q[4], w * q[5]), pack2(w * q[6], w * q[7]));
            }
            uint4* vs = hsp(wr_sp);
#pragma unroll
            for (int j = 0; j < 3; j++) {
                float w = wsj[j] * ns;
                red4h(vs + (long long)osj[j] * GRPH + g,
                      pack2(w * q[0], w * q[1]), pack2(w * q[2], w * q[3]),
                      pack2(w * q[4], w * q[5]), pack2(w * q[6], w * q[7]));
            }
        }
    }
    pdl_trigger();
}

// ---------------------------------------------------------------------------

static inline unsigned gridFor(long long n) { return (unsigned)((n + 255) / 256); }

// launch helper with PDL stream-serialization attribute
template <typename K, typename... Args>
static inline void pdlLaunch(unsigned grid, unsigned block, K kern, Args... args) {
    cudaLaunchConfig_t cfg = {};
    cfg.gridDim  = dim3(grid, 1, 1);
    cfg.blockDim = dim3(block, 1, 1);
    cfg.stream   = 0;
    cudaLaunchAttribute attr[1];
    attr[0].id = cudaLaunchAttributeProgrammaticStreamSerialization;
    attr[0].val.programmaticStreamSerializationAllowed = 1;
    cfg.attrs = attr;
    cfg.numAttrs = 1;
    cudaLaunchKernelEx(&cfg, kern, args...);
}

extern "C" void kernel_launch(void* const* d_in, const int* in_sizes, int n_in,
                              void* d_out, int out_size) {
    const float* unary  = (const float*)d_in[0];
    const float* ws_bi  = (const float*)d_in[1];
    const float* ws_sp  = (const float*)d_in[2];
    const int*   os_bi  = (const int*)  d_in[3];
    const int*   os_sp  = (const int*)  d_in[4];
    const int*   nbr_bi = (const int*)  d_in[5];
    const int*   nbr_sp = (const int*)  d_in[6];
    float*       out    = (float*)d_out;

    const int N   = in_sizes[1] / 6;
    const int Mbi = in_sizes[5] / 12;
    const int Msp = in_sizes[6] / 6;
    const float ALPHA_BI = 32.0f / 33.0f;  // 1/(1+2^-5)
    const float ALPHA_SP = 0.8f;           // 1/(1+2^-2)
    const float CB = 10.0f * ALPHA_BI;
    const float CS = 3.0f  * ALPHA_SP;
    const int B = 256;

    const long long NBH = (long long)(Mbi + 1) * GRPH;   // fp16 buffer in uint4s
    const long long NSH = (long long)(Msp + 1) * GRPH;

    // ---- prologue: normalization constants (fp32 1-channel chain) ----
    k_zero_fronts<<<gridFor((Mbi + 1) + (Msp + 1)), B>>>(Mbi + 1, Msp + 1);
    pdlLaunch(gridFor((long long)N * 9 + NBH + NSH), B, k_splat1z,
              ws_bi, os_bi, N * 6, ws_sp, os_sp, N * 3, NBH, NSH);
    int cb_ = 0, cs_ = 0;
    for (int j = 0; j < 6; j++) {
        int hassp = (j < 3);
        int bd = 1 - cb_;
        int sd = 1 - cs_;
        long long tot = (Mbi + 1) + (hassp ? (Msp + 1) : 0);
        pdlLaunch(gridFor(tot), B, k_blur1_both,
                  bd, cb_, nbr_bi + (long long)j * Mbi * 2, Mbi,
                  sd, cs_, nbr_sp + (long long)j * Msp * 2, Msp, hassp);
        cb_ = bd;
        if (hassp) cs_ = sd;
    }
    // bi 1-ch final in buffer cb_ (=0), sp in cs_ (=1)

    // ---- initial Q = softmax(-u): computes norms inline, splats into bi2/sp2 ----
    pdlLaunch(gridFor((long long)N * 4), B, k_update_splat,
              unary, out, ws_bi, os_bi, ws_sp, os_sp, N,
              /*usepair=*/0, /*to_ext=*/0, /*do_splat=*/1, /*do_norm=*/1,
              0, 0, /*wr_bi=*/2, /*wr_sp=*/2, CB, CS,
              cb_, cs_, ALPHA_BI, ALPHA_SP);

    // ---- mean-field iterations (triple-buffer rotation) ----
    int sB = 2, tB = 0, zB = 1;   // bi: splat-src / pong / to-zero
    int sS = 2, tS = 0, zS = 1;   // sp
    for (int it = 0; it < 5; it++) {
        int c = sB, csp = sS;
        for (int j = 0; j < 6; j++) {
            int hassp = (j < 3);
            int d   = (c   == sB) ? tB : sB;
            int dsp = (csp == sS) ? tS : sS;
            long long tot = NBH + (hassp ? NSH : 0) + ((j == 0) ? (NBH + NSH) : 0);
            if (j == 0) {
                pdlLaunch(gridFor(tot), B, k_blurHz,
                          d, c, nbr_bi + (long long)j * Mbi * 2, Mbi,
                          dsp, csp, nbr_sp + (long long)j * Msp * 2, Msp,
                          hassp, zB, NBH, zS, NSH);
            } else {
                pdlLaunch(gridFor(tot), B, k_blurHz,
                          d, c, nbr_bi + (long long)j * Mbi * 2, Mbi,
                          dsp, csp, nbr_sp + (long long)j * Msp * 2, Msp,
                          hassp, 0, 0LL, 0, 0LL);
            }
            c = d;
            if (hassp) csp = dsp;
        }
        // bi result in sB (6 flips), sp result in tS (3 flips)
        if (it < 4) {
            pdlLaunch(gridFor((long long)N * 4), B, k_update_splat,
                      unary, out, ws_bi, os_bi, ws_sp, os_sp, N,
                      /*usepair=*/1, /*to_ext=*/0, /*do_splat=*/1, /*do_norm=*/0,
                      sB, tS, /*wr_bi=*/zB, /*wr_sp=*/zS, CB, CS, 0, 0, 0.f, 0.f);
            int nB_ = zB; zB = sB; sB = nB_;                   // tB unchanged
            int nS_ = zS; zS = tS; tS = sS; sS = nS_;
        } else {
            pdlLaunch(gridFor((long long)N * 4), B, k_update_splat,
                      unary, out, ws_bi, os_bi, ws_sp, os_sp, N,
                      /*usepair=*/1, /*to_ext=*/1, /*do_splat=*/0, /*do_norm=*/0,
                      sB, tS, 0, 0, CB, CS, 0, 0, 0.f, 0.f);
        }
    }
}